// round 8
// baseline (speedup 1.0000x reference)
#include <cuda_runtime.h>
#include <math.h>

#define HID    128
#define NODEF  256
#define NMAX   512
#define NBINS  22
#define ETILE  128
#define TW     256
#define HPITCH 132  // h buffer row pitch

// ---------------- scratch (device globals; no allocations) ----------------
__device__ float g_n2e[NMAX * HID];
__device__ float g_A[NMAX * HID];          // A[i] = n2e[i]@W1[0:128] + b1 + flow[i]*W1[428]
__device__ float g_B[NMAX * HID];          // B[j] = n2e[j]@W1[128:256] + flow[j]*W1[429]
__device__ float g_R[(2 * NMAX - 1) * HID];// R[d+N-1] = relpos_feats(d)@W1[256:384]

// ---------------- f32x2 helpers ----------------
__device__ __forceinline__ unsigned long long fma2(unsigned long long a, unsigned long long b,
                                                   unsigned long long c) {
    unsigned long long d;
    asm("fma.rn.f32x2 %0, %1, %2, %3;" : "=l"(d) : "l"(a), "l"(b), "l"(c));
    return d;
}
__device__ __forceinline__ unsigned long long dup2(float x) {
    unsigned long long d;
    asm("mov.b64 %0, {%1, %1};" : "=l"(d) : "f"(x));
    return d;
}
__device__ __forceinline__ float2 unpk(unsigned long long a) {
    float2 r;
    asm("mov.b64 {%0, %1}, %2;" : "=f"(r.x), "=f"(r.y) : "l"(a));
    return r;
}

// ---------------- precompute kernels ----------------
__global__ void k_n2e(const float* __restrict__ nf, const float* __restrict__ W,
                      const float* __restrict__ b) {
    __shared__ float row[NODEF];
    const int i = blockIdx.x, c = threadIdx.x;
    row[c]       = nf[i * NODEF + c];
    row[c + 128] = nf[i * NODEF + 128 + c];
    __syncthreads();
    float acc = b[c];
#pragma unroll 8
    for (int k = 0; k < NODEF; k++) acc += row[k] * W[k * HID + c];
    g_n2e[i * HID + c] = acc;
}

__global__ void k_AB(const float* __restrict__ W1, const float* __restrict__ b1,
                     const float* __restrict__ flow) {
    __shared__ float row[HID];
    const int i = blockIdx.x, c = threadIdx.x;
    row[c] = g_n2e[i * HID + c];
    __syncthreads();
    const float fi = flow[i];
    float a  = b1[c] + fi * W1[428 * HID + c];
    float bb = fi * W1[429 * HID + c];
#pragma unroll 8
    for (int k = 0; k < HID; k++) {
        float v = row[k];
        a  += v * W1[k * HID + c];
        bb += v * W1[(128 + k) * HID + c];
    }
    g_A[i * HID + c] = a;
    g_B[i * HID + c] = bb;
}

__global__ void k_R(const float* __restrict__ Wrp, const float* __restrict__ brp,
                    const float* __restrict__ W1, int N) {
    __shared__ float emb[HID];
    __shared__ float rp[HID];
    const int c = threadIdx.x;
    const float d = (float)((int)blockIdx.x - (N - 1));
    if (c < 64) {
        float den = (float)pow(2056.0, (double)c * (1.0 / 64.0));
        float ang = (d * 3.14159274101257324f) / den;
        emb[c]      = (float)sin((double)ang);
        emb[c + 64] = (float)cos((double)ang);
    }
    __syncthreads();
    float acc = brp[c];
#pragma unroll 8
    for (int k = 0; k < HID; k++) acc += emb[k] * Wrp[k * HID + c];
    rp[c] = acc;
    __syncthreads();
    float r = 0.0f;
#pragma unroll 8
    for (int k = 0; k < HID; k++) r += rp[k] * W1[(256 + k) * HID + c];
    g_R[blockIdx.x * HID + c] = r;
}

// ---------------- distogram bin (matches jnp strict inequalities) ----------------
__device__ __forceinline__ int calc_bin(const float* __restrict__ p, int i, int j) {
    const float dx = __ldg(&p[3 * i + 0]) - __ldg(&p[3 * j + 0]);
    const float dy = __ldg(&p[3 * i + 1]) - __ldg(&p[3 * j + 1]);
    const float dz = __ldg(&p[3 * i + 2]) - __ldg(&p[3 * j + 2]);
    const float d = sqrtf((dx * dx + dy * dy) + dz * dz);
    const float step = (20.0f - 0.001f) / 21.0f;
    int bin = -1;
#pragma unroll
    for (int k = 0; k < NBINS; k++) {
        const float lo = 0.001f + (float)k * step;
        const float hi = (k == NBINS - 1) ? 1e8f : (0.001f + (float)(k + 1) * step);
        if (d > lo && d < hi) bin = k;
    }
    return bin;
}

// ---------------- GEMM core: 8 warps, warp tile 64 edges x 32 channels ----------
// per thread: 8 edges (4 f32x2 pairs) x 8 channels = 32 FFMA2/k.
// lane: er = lane>>2 (8 edge groups), cr = lane&3 (4 channel groups).
// Per LDS phase (8 lanes): h -> 2 distinct 16B (1 wf), W -> 4x16B in one 128B line (1 wf).
__device__ __forceinline__ void gemm_wt(const float* __restrict__ shin,
                                        const float* __restrict__ sW,
                                        int le, int lc, unsigned long long (&acc)[4][8]) {
#pragma unroll
    for (int ep = 0; ep < 4; ep++)
#pragma unroll
        for (int cc = 0; cc < 8; cc++) acc[ep][cc] = 0ULL;
#pragma unroll 2
    for (int k = 0; k < HID; k++) {
        const ulonglong2 hA = *reinterpret_cast<const ulonglong2*>(shin + k * HPITCH + le);
        const ulonglong2 hB = *reinterpret_cast<const ulonglong2*>(shin + k * HPITCH + le + 4);
        const float4 w0 = *reinterpret_cast<const float4*>(sW + k * HID + lc);
        const float4 w1 = *reinterpret_cast<const float4*>(sW + k * HID + lc + 4);
        unsigned long long hp[4] = {hA.x, hA.y, hB.x, hB.y};
        unsigned long long wd[8] = {dup2(w0.x), dup2(w0.y), dup2(w0.z), dup2(w0.w),
                                    dup2(w1.x), dup2(w1.y), dup2(w1.z), dup2(w1.w)};
#pragma unroll
        for (int ep = 0; ep < 4; ep++)
#pragma unroll
            for (int cc = 0; cc < 8; cc++)
                acc[ep][cc] = fma2(hp[ep], wd[cc], acc[ep][cc]);
    }
}

// ---------------- main persistent kernel ----------------
// smem (floats): W2 16384 | W3 16384 | Wtail 5632 | h 16896 (h1 -> h2 -> h3, reused)
//                | A 128 | b2 128 | b3 128 | g 128 | beta 128 | bins 256
#define SMEM_FLOATS 56192
#define SMEM_BYTES  (SMEM_FLOATS * 4)

__global__ void __launch_bounds__(TW, 1) k_main(
    const float* __restrict__ trans, const float* __restrict__ sctrans,
    const float* __restrict__ emask,
    const float* __restrict__ W2, const float* __restrict__ b2,
    const float* __restrict__ W3, const float* __restrict__ b3,
    const float* __restrict__ W1,
    const float* __restrict__ lng, const float* __restrict__ lnb,
    float* __restrict__ out, int N) {
    extern __shared__ float sm[];
    float* sW2 = sm;
    float* sW3 = sm + 16384;
    float* sWT = sm + 32768;   // 44*128: dist rows then sc rows
    float* sh  = sm + 38400;   // [128][HPITCH] transposed (h1,h2); reused as [128][HPITCH] edge-major h3
    float* sA  = sm + 55296;
    float* sb2 = sm + 55424;
    float* sb3 = sm + 55552;
    float* sg  = sm + 55680;
    float* sbt = sm + 55808;
    int* sbin1 = (int*)(sm + 55936);
    int* sbin2 = sbin1 + ETILE;

    const int tid = threadIdx.x;
    for (int idx = tid; idx < HID * HID; idx += TW) {
        sW2[idx] = W2[idx];
        sW3[idx] = W3[idx];
    }
    for (int idx = tid; idx < 44 * HID; idx += TW) sWT[idx] = W1[384 * HID + idx];
    if (tid < HID) {
        sb2[tid] = b2[tid];
        sb3[tid] = b3[tid];
        sg[tid]  = lng[tid];
        sbt[tid] = lnb[tid];
    }
    __syncthreads();

    const int lane = tid & 31;
    const int w = tid >> 5;                  // 8 warps
    const int eb = (w & 1) << 6;             // warp edge block (64 edges)
    const int cb = (w >> 1) << 5;            // warp channel block (32 channels)
    const int le = eb + ((lane >> 2) << 3);  // lane's 8 edges
    const int lc = cb + ((lane & 3) << 3);   // lane's 8 channels
    const int tilesPerRow = N / ETILE;
    const int ntiles = N * tilesPerRow;

    for (int t = blockIdx.x; t < ntiles; t += gridDim.x) {
        const int i = t / tilesPerRow;
        const int jb = (t - i * tilesPerRow) * ETILE;

        if (tid < ETILE) {
            const int j = jb + tid;
            sbin1[tid] = calc_bin(trans, i, j);
            sbin2[tid] = calc_bin(sctrans, i, j);
        } else {
            const int c = tid - ETILE;
            sA[c] = g_A[i * HID + c];
        }
        __syncthreads();

        // ---- h1 assembly (table adds + relu), transposed store ----
        {
            const int c = tid & 127;
            const float a = sA[c];
            for (int e = (tid >> 7); e < ETILE; e += 2) {
                const int j = jb + e;
                float v = a + __ldg(&g_B[j * HID + c]) +
                          __ldg(&g_R[(i - j + (N - 1)) * HID + c]);
                const int q1 = sbin1[e];
                if (q1 >= 0) v += sWT[q1 * HID + c];
                const int q2 = sbin2[e];
                if (q2 >= 0) v += sWT[(NBINS + q2) * HID + c];
                sh[c * HPITCH + e] = fmaxf(v, 0.0f);
            }
        }
        __syncthreads();

        // ---- layer 2: h2 = relu(h1 @ W2 + b2); overwrite h buffer after barrier ----
        {
            unsigned long long acc[4][8];
            gemm_wt(sh, sW2, le, lc, acc);
            __syncthreads();   // all h1 reads complete before overwrite
#pragma unroll
            for (int cc = 0; cc < 8; cc++) {
                const float b = sb2[lc + cc];
                float2 p0 = unpk(acc[0][cc]);
                float2 p1 = unpk(acc[1][cc]);
                float2 p2 = unpk(acc[2][cc]);
                float2 p3 = unpk(acc[3][cc]);
                float4 q0 = make_float4(fmaxf(p0.x + b, 0.f), fmaxf(p0.y + b, 0.f),
                                        fmaxf(p1.x + b, 0.f), fmaxf(p1.y + b, 0.f));
                float4 q1 = make_float4(fmaxf(p2.x + b, 0.f), fmaxf(p2.y + b, 0.f),
                                        fmaxf(p3.x + b, 0.f), fmaxf(p3.y + b, 0.f));
                float* d = &sh[(lc + cc) * HPITCH + le];
                *reinterpret_cast<float4*>(d) = q0;
                *reinterpret_cast<float4*>(d + 4) = q1;
            }
        }
        __syncthreads();

        // ---- layer 3: h3 = h2 @ W3 + b3; edge-major store into same buffer ----
        {
            unsigned long long acc[4][8];
            gemm_wt(sh, sW3, le, lc, acc);
            __syncthreads();   // all h2 reads complete before overwrite
#pragma unroll
            for (int ep = 0; ep < 4; ep++) {
                float2 p[8];
#pragma unroll
                for (int cc = 0; cc < 8; cc++) {
                    p[cc] = unpk(acc[ep][cc]);
                    p[cc].x += sb3[lc + cc];
                    p[cc].y += sb3[lc + cc];
                }
                float* d0 = &sh[(le + 2 * ep) * HPITCH + lc];
                float* d1 = &sh[(le + 2 * ep + 1) * HPITCH + lc];
                *reinterpret_cast<float4*>(d0)     = make_float4(p[0].x, p[1].x, p[2].x, p[3].x);
                *reinterpret_cast<float4*>(d0 + 4) = make_float4(p[4].x, p[5].x, p[6].x, p[7].x);
                *reinterpret_cast<float4*>(d1)     = make_float4(p[0].y, p[1].y, p[2].y, p[3].y);
                *reinterpret_cast<float4*>(d1 + 4) = make_float4(p[4].y, p[5].y, p[6].y, p[7].y);
            }
        }
        __syncthreads();

        // ---- LayerNorm + mask + store: 2 threads per edge, 64 channels each ----
        {
            const int e = tid >> 1;           // 0..127
            const int cbase = (tid & 1) << 6; // 0 or 64
            float vals[64];
            float s = 0.0f;
#pragma unroll
            for (int m4 = 0; m4 < 16; m4++) {
                float4 r = *reinterpret_cast<const float4*>(&sh[e * HPITCH + cbase + 4 * m4]);
                vals[4 * m4 + 0] = r.x; vals[4 * m4 + 1] = r.y;
                vals[4 * m4 + 2] = r.z; vals[4 * m4 + 3] = r.w;
                s += ((r.x + r.y) + (r.z + r.w));
            }
            s += __shfl_xor_sync(0xffffffffu, s, 1);
            const float mu = s * (1.0f / 128.0f);
            float q = 0.0f;
#pragma unroll
            for (int m = 0; m < 64; m++) {
                vals[m] -= mu;
                q += vals[m] * vals[m];
            }
            q += __shfl_xor_sync(0xffffffffu, q, 1);
            const float rstd = 1.0f / sqrtf(q * (1.0f / 128.0f) + 1e-5f);
            const float msk = __ldg(&emask[i * N + jb + e]);
            float* op = &out[((size_t)(i * N + jb + e)) * HID + cbase];
#pragma unroll
            for (int m4 = 0; m4 < 16; m4++) {
                float4 o;
                o.x = (vals[4 * m4 + 0] * rstd * sg[cbase + 4 * m4 + 0] + sbt[cbase + 4 * m4 + 0]) * msk;
                o.y = (vals[4 * m4 + 1] * rstd * sg[cbase + 4 * m4 + 1] + sbt[cbase + 4 * m4 + 1]) * msk;
                o.z = (vals[4 * m4 + 2] * rstd * sg[cbase + 4 * m4 + 2] + sbt[cbase + 4 * m4 + 2]) * msk;
                o.w = (vals[4 * m4 + 3] * rstd * sg[cbase + 4 * m4 + 3] + sbt[cbase + 4 * m4 + 3]) * msk;
                *reinterpret_cast<float4*>(op + 4 * m4) = o;
            }
        }
        __syncthreads();   // h buffer and bins reused next iteration
    }
}

// ---------------- launch ----------------
extern "C" void kernel_launch(void* const* d_in, const int* in_sizes, int n_in,
                              void* d_out, int out_size) {
    const float* nf     = (const float*)d_in[0];
    const float* trans  = (const float*)d_in[1];
    const float* sct    = (const float*)d_in[2];
    const float* emask  = (const float*)d_in[3];
    const float* flow   = (const float*)d_in[4];
    const float* W_n2e  = (const float*)d_in[5];
    const float* b_n2e  = (const float*)d_in[6];
    const float* W_rp   = (const float*)d_in[7];
    const float* b_rp   = (const float*)d_in[8];
    const float* W1     = (const float*)d_in[9];
    const float* b1     = (const float*)d_in[10];
    const float* W2     = (const float*)d_in[11];
    const float* b2     = (const float*)d_in[12];
    const float* W3     = (const float*)d_in[13];
    const float* b3     = (const float*)d_in[14];
    const float* lng    = (const float*)d_in[15];
    const float* lnb    = (const float*)d_in[16];
    float* out = (float*)d_out;

    const int N = in_sizes[4];  // flow_mask length

    k_n2e<<<N, 128>>>(nf, W_n2e, b_n2e);
    k_AB<<<N, 128>>>(W1, b1, flow);
    k_R<<<2 * N - 1, 128>>>(W_rp, b_rp, W1, N);

    cudaFuncSetAttribute((const void*)k_main,
                         cudaFuncAttributeMaxDynamicSharedMemorySize, SMEM_BYTES);
    k_main<<<152, TW, SMEM_BYTES>>>(trans, sct, emask, W2, b2, W3, b3, W1,
                                    lng, lnb, out, N);
}

// round 10
// speedup vs baseline: 1.4858x; 1.4858x over previous
#include <cuda_runtime.h>
#include <cuda_bf16.h>
#include <math.h>
#include <stdint.h>

#define HID   128
#define NODEF 256
#define NBINS 22
#define ETILE 128
#define TW    256
#define WTP   132

// ---- smem byte offsets ----
#define OFF_W2HI 0
#define OFF_W2LO 32768
#define OFF_W3HI 65536
#define OFF_W3LO 98304
#define OFF_AHI  131072
#define OFF_ALO  163840
#define OFF_WT   196608                  // float[46][WTP], rows 44/45 zero
#define OFF_SA   (OFF_WT + 46*WTP*4)     // 220896
#define OFF_SB2  (OFF_SA + 512)
#define OFF_SB3  (OFF_SB2 + 512)
#define OFF_SG   (OFF_SB3 + 512)
#define OFF_SBT  (OFF_SG + 512)
#define OFF_MSK  (OFF_SBT + 512)
#define OFF_BIN1 (OFF_MSK + 512)
#define OFF_BIN2 (OFF_BIN1 + 512)
#define OFF_RSUM (OFF_BIN2 + 512)        // float[2][128]
#define OFF_RSQ  (OFF_RSUM + 1024)       // float[2][128]
#define SMEM_BYTES (OFF_RSQ + 1024)      // 227040

__device__ float g_A[512 * HID];
__device__ float g_B[512 * HID];
__device__ float g_R[1023 * HID];

// ---- helpers ----
__device__ __forceinline__ uint32_t pk2(float a, float b) {  // lo = a, hi = b
    uint32_t r;
    asm("cvt.rn.bf16x2.f32 %0, %1, %2;" : "=r"(r) : "f"(b), "f"(a));
    return r;
}
__device__ __forceinline__ float2 up2(uint32_t p) {
    float2 r;
    asm("{ .reg .b16 l,h; mov.b32 {l,h}, %2; cvt.f32.bf16 %0, l; cvt.f32.bf16 %1, h; }"
        : "=f"(r.x), "=f"(r.y) : "r"(p));
    return r;
}
__device__ __forceinline__ void mma16816(float (&d)[4], const uint4& a, const uint2& b) {
    asm volatile("mma.sync.aligned.m16n8k16.row.col.f32.bf16.bf16.f32 "
                 "{%0,%1,%2,%3}, {%4,%5,%6,%7}, {%8,%9}, {%0,%1,%2,%3};"
                 : "+f"(d[0]), "+f"(d[1]), "+f"(d[2]), "+f"(d[3])
                 : "r"(a.x), "r"(a.y), "r"(a.z), "r"(a.w), "r"(b.x), "r"(b.y));
}

// ---- precompute ----
__global__ void k_pre(const float* __restrict__ nf, const float* __restrict__ Wn,
                      const float* __restrict__ bn, const float* __restrict__ W1,
                      const float* __restrict__ b1, const float* __restrict__ flow) {
    __shared__ float row[NODEF];
    __shared__ float n2e[HID];
    const int i = blockIdx.x, c = threadIdx.x;
    row[c] = nf[i * NODEF + c];
    row[c + 128] = nf[i * NODEF + 128 + c];
    __syncthreads();
    float acc = bn[c];
#pragma unroll 8
    for (int k = 0; k < NODEF; k++) acc += row[k] * Wn[k * HID + c];
    n2e[c] = acc;
    __syncthreads();
    const float fi = flow[i];
    float a = b1[c] + fi * W1[428 * HID + c];
    float bb = fi * W1[429 * HID + c];
#pragma unroll 8
    for (int k = 0; k < HID; k++) {
        float v = n2e[k];
        a += v * W1[k * HID + c];
        bb += v * W1[(128 + k) * HID + c];
    }
    g_A[i * HID + c] = a;
    g_B[i * HID + c] = bb;
}

__global__ void k_R(const float* __restrict__ Wrp, const float* __restrict__ brp,
                    const float* __restrict__ W1, int N) {
    __shared__ float emb[HID];
    __shared__ float rp[HID];
    const int c = threadIdx.x;
    const float d = (float)((int)blockIdx.x - (N - 1));
    if (c < 64) {
        float den = (float)pow(2056.0, (double)c * (1.0 / 64.0));
        float ang = (d * 3.14159274101257324f) / den;
        emb[c] = (float)sin((double)ang);
        emb[c + 64] = (float)cos((double)ang);
    }
    __syncthreads();
    float acc = brp[c];
#pragma unroll 8
    for (int k = 0; k < HID; k++) acc += emb[k] * Wrp[k * HID + c];
    rp[c] = acc;
    __syncthreads();
    float r = 0.0f;
#pragma unroll 8
    for (int k = 0; k < HID; k++) r += rp[k] * W1[(256 + k) * HID + c];
    g_R[blockIdx.x * HID + c] = r;
}

__device__ __forceinline__ int calc_bin(const float* __restrict__ p, int i, int j) {
    const float dx = __ldg(&p[3 * i + 0]) - __ldg(&p[3 * j + 0]);
    const float dy = __ldg(&p[3 * i + 1]) - __ldg(&p[3 * j + 1]);
    const float dz = __ldg(&p[3 * i + 2]) - __ldg(&p[3 * j + 2]);
    const float d = sqrtf((dx * dx + dy * dy) + dz * dz);
    const float step = (20.0f - 0.001f) / 21.0f;
    int bin = -1;
#pragma unroll
    for (int k = 0; k < NBINS; k++) {
        const float lo = 0.001f + (float)k * step;
        const float hi = (k == NBINS - 1) ? 1e8f : (0.001f + (float)(k + 1) * step);
        if (d > lo && d < hi) bin = k;
    }
    return bin;
}

// one layer: acc[2][8][4] += split-bf16( A[128x128] @ W[128x128] ), warp tile 32e x 64c
__device__ __forceinline__ void gemm_mma(const char* smc, int woff_hi, int woff_lo,
                                         int wm, int wn, int lane, float (&acc)[2][8][4]) {
#pragma unroll
    for (int m = 0; m < 2; m++)
#pragma unroll
        for (int nt = 0; nt < 8; nt++)
#pragma unroll
            for (int q = 0; q < 4; q++) acc[m][nt][q] = 0.0f;
    const int mt0 = 2 * wm, mt1 = 2 * wm + 1;
#pragma unroll 2
    for (int ks = 0; ks < 8; ks++) {
        const uint4 ah0 = *(const uint4*)(smc + OFF_AHI + ((mt0 * 8 + ks) * 32 + lane) * 16);
        const uint4 al0 = *(const uint4*)(smc + OFF_ALO + ((mt0 * 8 + ks) * 32 + lane) * 16);
        const uint4 ah1 = *(const uint4*)(smc + OFF_AHI + ((mt1 * 8 + ks) * 32 + lane) * 16);
        const uint4 al1 = *(const uint4*)(smc + OFF_ALO + ((mt1 * 8 + ks) * 32 + lane) * 16);
#pragma unroll
        for (int nt = 0; nt < 8; nt++) {
            const int ntg = wn * 8 + nt;
            const uint2 bh = *(const uint2*)(smc + woff_hi + ((ntg * 8 + ks) * 32 + lane) * 8);
            const uint2 bl = *(const uint2*)(smc + woff_lo + ((ntg * 8 + ks) * 32 + lane) * 8);
            mma16816(acc[0][nt], ah0, bh);
            mma16816(acc[0][nt], ah0, bl);
            mma16816(acc[0][nt], al0, bh);
            mma16816(acc[1][nt], ah1, bh);
            mma16816(acc[1][nt], ah1, bl);
            mma16816(acc[1][nt], al1, bh);
        }
    }
}

// ---- main persistent kernel ----
__global__ void __launch_bounds__(TW, 1) k_main(
    const float* __restrict__ trans, const float* __restrict__ sctrans,
    const float* __restrict__ emask, const float* __restrict__ W1,
    const float* __restrict__ W2, const float* __restrict__ b2,
    const float* __restrict__ W3, const float* __restrict__ b3,
    const float* __restrict__ lng, const float* __restrict__ lnb,
    float* __restrict__ out, int N) {
    extern __shared__ char smc[];
    float* sWT  = (float*)(smc + OFF_WT);
    float* sA   = (float*)(smc + OFF_SA);
    float* smk  = (float*)(smc + OFF_MSK);
    int* sbin1  = (int*)(smc + OFF_BIN1);
    int* sbin2  = (int*)(smc + OFF_BIN2);
    float* rsum = (float*)(smc + OFF_RSUM);
    float* rsq  = (float*)(smc + OFF_RSQ);

    const int tid = threadIdx.x, lane = tid & 31, wid = tid >> 5;
    const int wm = wid & 3, wn = wid >> 2;      // warp tile: edges [64wm,64wm+32), ch [64wn,64wn+64)
    const int gq = lane >> 2, tq = lane & 3;

    // one-time: W2/W3 -> bf16 hi/lo B-fragment layout; W1 tail; vectors
    for (int idx = tid; idx < 64 * HID; idx += TW) {   // 8192 k-pair words
        const int n = idx >> 6, k = (idx & 63) * 2;
        const int nt = n >> 3, gg = n & 7;
        const int t = (k >> 1) & 3, ks = k >> 4, r = (k >> 3) & 1;
        const int woff = ((((nt * 8 + ks) * 32 + 4 * gg + t) * 2) + r) * 4;
        {
            const float w0 = W2[k * HID + n], w1 = W2[(k + 1) * HID + n];
            const uint32_t hi = pk2(w0, w1);
            const float2 f = up2(hi);
            *(uint32_t*)(smc + OFF_W2HI + woff) = hi;
            *(uint32_t*)(smc + OFF_W2LO + woff) = pk2(w0 - f.x, w1 - f.y);
        }
        {
            const float w0 = W3[k * HID + n], w1 = W3[(k + 1) * HID + n];
            const uint32_t hi = pk2(w0, w1);
            const float2 f = up2(hi);
            *(uint32_t*)(smc + OFF_W3HI + woff) = hi;
            *(uint32_t*)(smc + OFF_W3LO + woff) = pk2(w0 - f.x, w1 - f.y);
        }
    }
    for (int idx = tid; idx < 46 * HID; idx += TW) {
        const int q = idx >> 7, c = idx & 127;
        sWT[q * WTP + c] = (q < 44) ? W1[(384 + q) * HID + c] : 0.0f;
    }
    if (tid < HID) {
        ((float*)(smc + OFF_SB2))[tid] = b2[tid];
        ((float*)(smc + OFF_SB3))[tid] = b3[tid];
        ((float*)(smc + OFF_SG))[tid]  = lng[tid];
        ((float*)(smc + OFF_SBT))[tid] = lnb[tid];
    }
    __syncthreads();

    const int tpr = N / ETILE, ntiles = N * tpr;

    for (int t0 = blockIdx.x; t0 < ntiles; t0 += gridDim.x) {
        const int i = t0 / tpr;
        const int jb = (t0 - i * tpr) * ETILE;

        if (tid < ETILE) {
            const int j = jb + tid;
            const int q1 = calc_bin(trans, i, j);
            const int q2 = calc_bin(sctrans, i, j);
            sbin1[tid] = (q1 < 0 ? 44 : q1) * WTP;
            sbin2[tid] = (q2 < 0 ? 44 : 22 + q2) * WTP;
            smk[tid] = emask[i * N + j];
        } else {
            sA[tid - 128] = g_A[i * HID + (tid - 128)];
        }
        __syncthreads();

        // ---- phase 0: assemble h1, split hi/lo, store in A-fragment order ----
        {
            const int e = tid >> 1, chb = (tid & 1) * 64;
            const int mt = e >> 4, g8 = e & 7, rowhi = (e >> 3) & 1;
            const int j = jb + e;
            const float* bp = &g_B[j * HID];
            const float* rp = &g_R[(size_t)(i - j + N - 1) * HID];
            const float* t1p = &sWT[sbin1[e]];
            const float* t2p = &sWT[sbin2[e]];
#pragma unroll
            for (int cg = 0; cg < 8; cg++) {
                const int c0 = chb + cg * 8;
                float v[8];
#pragma unroll
                for (int h4 = 0; h4 < 2; h4++) {
                    const int c = c0 + 4 * h4;
                    const float4 av = *(const float4*)&sA[c];
                    const float4 bv = *(const float4*)&bp[c];
                    const float4 rv = *(const float4*)&rp[c];
                    const float4 w1v = *(const float4*)&t1p[c];
                    const float4 w2v = *(const float4*)&t2p[c];
                    v[4 * h4 + 0] = fmaxf(av.x + bv.x + rv.x + w1v.x + w2v.x, 0.0f);
                    v[4 * h4 + 1] = fmaxf(av.y + bv.y + rv.y + w1v.y + w2v.y, 0.0f);
                    v[4 * h4 + 2] = fmaxf(av.z + bv.z + rv.z + w1v.z + w2v.z, 0.0f);
                    v[4 * h4 + 3] = fmaxf(av.w + bv.w + rv.w + w1v.w + w2v.w, 0.0f);
                }
                const int ks = c0 >> 4, khalf = (c0 >> 3) & 1;
                const int r = khalf * 2 + rowhi;
                const int base = ((mt * 8 + ks) * 32 + 4 * g8) * 16 + r * 4;
#pragma unroll
                for (int tt = 0; tt < 4; tt++) {
                    const uint32_t hi = pk2(v[2 * tt], v[2 * tt + 1]);
                    const float2 f = up2(hi);
                    *(uint32_t*)(smc + OFF_AHI + base + tt * 16) = hi;
                    *(uint32_t*)(smc + OFF_ALO + base + tt * 16) =
                        pk2(v[2 * tt] - f.x, v[2 * tt + 1] - f.y);
                }
            }
        }
        __syncthreads();

        float acc[2][8][4];

        // ---- layer 2 GEMM + epilogue (bias+relu+resplit into A tiles) ----
        gemm_mma(smc, OFF_W2HI, OFF_W2LO, wm, wn, lane, acc);
        __syncthreads();   // all A reads done before overwrite
#pragma unroll
        for (int m = 0; m < 2; m++) {
            const int mtg = 2 * wm + m;
#pragma unroll
            for (int nt = 0; nt < 8; nt++) {
                const int col = wn * 64 + nt * 8 + 2 * tq;
                const float2 bb = *(const float2*)(smc + OFF_SB2 + col * 4);
                const float v0 = fmaxf(acc[m][nt][0] + bb.x, 0.0f);
                const float v1 = fmaxf(acc[m][nt][1] + bb.y, 0.0f);
                const float v2 = fmaxf(acc[m][nt][2] + bb.x, 0.0f);
                const float v3 = fmaxf(acc[m][nt][3] + bb.y, 0.0f);
                const uint32_t hi0 = pk2(v0, v1);
                const float2 f0 = up2(hi0);
                const uint32_t lo0 = pk2(v0 - f0.x, v1 - f0.y);
                const uint32_t hi1 = pk2(v2, v3);
                const float2 f1 = up2(hi1);
                const uint32_t lo1 = pk2(v2 - f1.x, v3 - f1.y);
                const int ks = (wn * 8 + nt) >> 1, roff = ((wn * 8 + nt) & 1) * 2;
                const int boff = (((mtg * 8 + ks) * 32 + lane) * 4 + roff) * 4;
                *(uint2*)(smc + OFF_AHI + boff) = make_uint2(hi0, hi1);
                *(uint2*)(smc + OFF_ALO + boff) = make_uint2(lo0, lo1);
            }
        }
        __syncthreads();

        // ---- layer 3 GEMM ----
        gemm_mma(smc, OFF_W3HI, OFF_W3LO, wm, wn, lane, acc);

        // ---- bias + LayerNorm + mask + store ----
        {
            float s[2][2] = {{0, 0}, {0, 0}}, q[2][2] = {{0, 0}, {0, 0}};
#pragma unroll
            for (int m = 0; m < 2; m++)
#pragma unroll
                for (int nt = 0; nt < 8; nt++) {
                    const int col = wn * 64 + nt * 8 + 2 * tq;
                    const float2 bb = *(const float2*)(smc + OFF_SB3 + col * 4);
                    acc[m][nt][0] += bb.x;
                    acc[m][nt][1] += bb.y;
                    acc[m][nt][2] += bb.x;
                    acc[m][nt][3] += bb.y;
                    s[m][0] += acc[m][nt][0] + acc[m][nt][1];
                    s[m][1] += acc[m][nt][2] + acc[m][nt][3];
                    q[m][0] += acc[m][nt][0] * acc[m][nt][0] + acc[m][nt][1] * acc[m][nt][1];
                    q[m][1] += acc[m][nt][2] * acc[m][nt][2] + acc[m][nt][3] * acc[m][nt][3];
                }
#pragma unroll
            for (int m = 0; m < 2; m++)
#pragma unroll
                for (int h = 0; h < 2; h++) {
                    s[m][h] += __shfl_xor_sync(0xffffffffu, s[m][h], 1);
                    s[m][h] += __shfl_xor_sync(0xffffffffu, s[m][h], 2);
                    q[m][h] += __shfl_xor_sync(0xffffffffu, q[m][h], 1);
                    q[m][h] += __shfl_xor_sync(0xffffffffu, q[m][h], 2);
                }
            if (tq == 0) {
#pragma unroll
                for (int m = 0; m < 2; m++)
#pragma unroll
                    for (int h = 0; h < 2; h++) {
                        const int row = (2 * wm + m) * 16 + gq + 8 * h;
                        rsum[wn * 128 + row] = s[m][h];
                        rsq[wn * 128 + row] = q[m][h];
                    }
            }
            __syncthreads();
#pragma unroll
            for (int m = 0; m < 2; m++)
#pragma unroll
                for (int h = 0; h < 2; h++) {
                    const int row = (2 * wm + m) * 16 + gq + 8 * h;
                    const float S = rsum[row] + rsum[128 + row];
                    const float Q = rsq[row] + rsq[128 + row];
                    const float mu = S * (1.0f / 128.0f);
                    const float var = Q * (1.0f / 128.0f) - mu * mu;
                    const float rstd = rsqrtf(var + 1e-5f);
                    const float msk = smk[row];
                    float* op = &out[((size_t)(i * N + jb + row)) * HID];
#pragma unroll
                    for (int nt = 0; nt < 8; nt++) {
                        const int col = wn * 64 + nt * 8 + 2 * tq;
                        const float2 gg = *(const float2*)(smc + OFF_SG + col * 4);
                        const float2 bt = *(const float2*)(smc + OFF_SBT + col * 4);
                        const float a = acc[m][nt][2 * h + 0];
                        const float b = acc[m][nt][2 * h + 1];
                        float2 o;
                        o.x = ((a - mu) * rstd * gg.x + bt.x) * msk;
                        o.y = ((b - mu) * rstd * gg.y + bt.y) * msk;
                        *(float2*)(op + col) = o;
                    }
                }
        }
        __syncthreads();   // A tiles / bins / red reused next iteration
    }
}

// ---- launch ----
extern "C" void kernel_launch(void* const* d_in, const int* in_sizes, int n_in,
                              void* d_out, int out_size) {
    const float* nf    = (const float*)d_in[0];
    const float* trans = (const float*)d_in[1];
    const float* sct   = (const float*)d_in[2];
    const float* emask = (const float*)d_in[3];
    const float* flow  = (const float*)d_in[4];
    const float* W_n2e = (const float*)d_in[5];
    const float* b_n2e = (const float*)d_in[6];
    const float* W_rp  = (const float*)d_in[7];
    const float* b_rp  = (const float*)d_in[8];
    const float* W1    = (const float*)d_in[9];
    const float* b1    = (const float*)d_in[10];
    const float* W2    = (const float*)d_in[11];
    const float* b2    = (const float*)d_in[12];
    const float* W3    = (const float*)d_in[13];
    const float* b3    = (const float*)d_in[14];
    const float* lng   = (const float*)d_in[15];
    const float* lnb   = (const float*)d_in[16];
    float* out = (float*)d_out;

    const int N = in_sizes[4];

    k_pre<<<N, 128>>>(nf, W_n2e, b_n2e, W1, b1, flow);
    k_R<<<2 * N - 1, 128>>>(W_rp, b_rp, W1, N);

    cudaFuncSetAttribute((const void*)k_main,
                         cudaFuncAttributeMaxDynamicSharedMemorySize, SMEM_BYTES);
    k_main<<<152, TW, SMEM_BYTES>>>(trans, sct, emask, W1, W2, b2, W3, b3,
                                    lng, lnb, out, N);
}